// round 2
// baseline (speedup 1.0000x reference)
#include <cuda_runtime.h>

#define HEADS 8
#define DH    64
#define NPIX  1024
#define CC    512
#define NB    8
#define NBH   64

typedef unsigned long long u64;

// ---- scratch (device globals: allocation-guard-safe) ----
__device__ __align__(16) float g_q[NBH * NPIX * DH];   // [bh][n][d]
__device__ __align__(16) float g_k[NBH * NPIX * DH];   // [bh][n][d]
__device__ __align__(16) float g_v[NBH * DH * NPIX];   // [bh][d][n]  (transposed!)
__device__ __align__(16) float g_p[HEADS * NPIX * DH]; // [h][n][d]

// ---- packed f32x2 helpers (Blackwell FFMA2 path) ----
__device__ __forceinline__ void ffma2(u64 &c, u64 a, u64 b) {
    asm("fma.rn.f32x2 %0, %1, %2, %0;" : "+l"(c) : "l"(a), "l"(b));
}
__device__ __forceinline__ u64 pack2(float x, float y) {
    u64 r; asm("mov.b64 %0, {%1, %2};" : "=l"(r) : "f"(x), "f"(y)); return r;
}
__device__ __forceinline__ void unpack2(u64 v, float &x, float &y) {
    asm("mov.b64 {%0, %1}, %2;" : "=f"(x), "=f"(y) : "l"(v));
}
__device__ __forceinline__ u64 mul2(u64 a, u64 b) {
    u64 r; asm("mul.rn.f32x2 %0, %1, %2;" : "=l"(r) : "l"(a), "l"(b)); return r;
}

// ================= pos = rel_h + rel_w -> g_p[h][n][d] =================
__global__ void pos_kernel(const float *__restrict__ rel_h,
                           const float *__restrict__ rel_w) {
    int idx = blockIdx.x * 256 + threadIdx.x;       // (h*1024+n)*64+d
    int d  = idx & 63;
    int n  = (idx >> 6) & 1023;
    int h  = idx >> 16;
    int w  = n >> 5;
    int hh = n & 31;
    g_p[idx] = rel_h[(h * DH + d) * 32 + hh] + rel_w[(h * DH + d) * 32 + w];
}

// ================= projection GEMMs =================
// Block tile: 128 pixels (m) x 64 out-channels (o) x k16. 256 threads.
// Thread: tm = t&15 owns m in {2tm+32g}+{0,1} (4 packed pairs), to = t>>4 owns o = 4to+j.
// f32x2 packing along free m-dim; B duplicated in smem so no MOV dups.
__global__ __launch_bounds__(256) void proj_kernel(
    const float *__restrict__ x,  const float *__restrict__ dsrc,
    const float *__restrict__ Wq, const float *__restrict__ bq,
    const float *__restrict__ Wk, const float *__restrict__ bk,
    const float *__restrict__ Wv, const float *__restrict__ bv) {
    const int p = blockIdx.z;
    const int b = blockIdx.y;
    const float *src  = (p == 0) ? x  : dsrc;
    const float *W    = (p == 0) ? Wq : (p == 1 ? Wk : Wv);
    const float *bias = (p == 0) ? bq : (p == 1 ? bk : bv);
    float *dst        = (p == 0) ? g_q : (p == 1 ? g_k : g_v);

    const int m0 = (blockIdx.x >> 3) * 128;
    const int o0 = (blockIdx.x & 7) * 64;

    __shared__ float As[16 * 130];    // [k][m], m-contiguous, stride 130
    __shared__ float Bs2[16 * 132];   // [k][2o] duplicated pairs, stride 132

    const int t  = threadIdx.x;
    const int tm = t & 15;
    const int to = t >> 4;

    u64 acc2[4][4];
    #pragma unroll
    for (int g = 0; g < 4; g++)
        #pragma unroll
        for (int j = 0; j < 4; j++) acc2[g][j] = 0ull;

    const float *srcb = src + (size_t)b * CC * NPIX;

    for (int kt = 0; kt < 32; kt++) {
        const int k0 = kt * 16;
        // stage A: x[b][k0+k][m0..m0+127]  (coalesced LDG.128, float2 STS)
        #pragma unroll
        for (int l2 = 0; l2 < 2; l2++) {
            int c = t + l2 * 256;
            int k = c >> 5, m4 = (c & 31) * 4;
            float4 xv = *(const float4 *)&srcb[(size_t)(k0 + k) * NPIX + m0 + m4];
            float *ar = &As[k * 130 + m4];
            *(float2 *)ar       = make_float2(xv.x, xv.y);
            *(float2 *)(ar + 2) = make_float2(xv.z, xv.w);
        }
        // stage B duplicated: W[o0+o][k0..k0+15]
        {
            int o = t >> 2, k4 = (t & 3) * 4;
            float4 wv = *(const float4 *)&W[(size_t)(o0 + o) * CC + k0 + k4];
            float vals[4] = {wv.x, wv.y, wv.z, wv.w};
            #pragma unroll
            for (int e = 0; e < 4; e++) {
                Bs2[(k4 + e) * 132 + 2 * o]     = vals[e];
                Bs2[(k4 + e) * 132 + 2 * o + 1] = vals[e];
            }
        }
        __syncthreads();
        #pragma unroll 4
        for (int k = 0; k < 16; k++) {
            u64 a2[4], b2[4];
            #pragma unroll
            for (int g = 0; g < 4; g++)
                a2[g] = *(const u64 *)&As[k * 130 + 2 * tm + 32 * g];
            #pragma unroll
            for (int j = 0; j < 4; j++)
                b2[j] = *(const u64 *)&Bs2[k * 132 + 8 * to + 2 * j];
            #pragma unroll
            for (int g = 0; g < 4; g++)
                #pragma unroll
                for (int j = 0; j < 4; j++) ffma2(acc2[g][j], a2[g], b2[j]);
        }
        __syncthreads();
    }

    // epilogue
    float bia[4];
    #pragma unroll
    for (int j = 0; j < 4; j++) bia[j] = bias[o0 + to * 4 + j];
    const int head = o0 >> 6;           // o0 multiple of 64
    const int d0   = to * 4;
    const int bh   = b * 8 + head;

    if (p < 2) {
        float *dbase = dst + (size_t)bh * NPIX * DH;
        #pragma unroll
        for (int g = 0; g < 4; g++) {
            int mm = m0 + 2 * tm + 32 * g;
            float lo[4], hi[4];
            #pragma unroll
            for (int j = 0; j < 4; j++) {
                float l_, h_; unpack2(acc2[g][j], l_, h_);
                lo[j] = l_ + bia[j]; hi[j] = h_ + bia[j];
            }
            *(float4 *)&dbase[(size_t)mm * DH + d0] =
                make_float4(lo[0], lo[1], lo[2], lo[3]);
            *(float4 *)&dbase[(size_t)(mm + 1) * DH + d0] =
                make_float4(hi[0], hi[1], hi[2], hi[3]);
        }
    } else {
        // V transposed: dst[bh][d][n]; pair (m, m+1) -> contiguous STG.64
        float *dbase = dst + (size_t)bh * DH * NPIX;
        #pragma unroll
        for (int g = 0; g < 4; g++) {
            int mm = m0 + 2 * tm + 32 * g;
            #pragma unroll
            for (int j = 0; j < 4; j++) {
                float l_, h_; unpack2(acc2[g][j], l_, h_);
                *(float2 *)&dbase[(size_t)(d0 + j) * NPIX + mm] =
                    make_float2(l_ + bia[j], h_ + bia[j]);
            }
        }
    }
}

// ================= fused attention =================
// Block: (query tile of 64, bh). 256 threads: tx = t&15, ty = t>>4.
// S[i][j] = a_i . b_j, a=[q_i|pos_i], b=[k_j|q_j], reduce 128 (f32x2 packed).
// Thread owns i in {16ii+ty}, j in {16jj+tx} for S; d in {16dd+tx} for O.
#define ATTN_SMEM ((2 * 64 * 130 + 64 * 66 + 64 * 80) * 4)

__global__ __launch_bounds__(256, 2) void attn_kernel(float *__restrict__ out) {
    extern __shared__ float sm[];
    float *as = sm;                  // [64][130]: [q_i | pos_i]
    float *bs = as + 64 * 130;       // [64][130]: [k_j | q_j]
    float *vT = bs + 64 * 130;       // [64][66]:  v^T [d][j]; reused as O^T [d][i]
    float *ps = vT + 64 * 66;        // [64][80]:  P [i][j]

    const int t  = threadIdx.x;
    const int tx = t & 15;
    const int ty = t >> 4;
    const int i0 = blockIdx.x * 64;
    const int bh = blockIdx.y;
    const int h  = bh & 7;

    const float *qb = g_q + (size_t)bh * NPIX * DH;
    const float *kb = g_k + (size_t)bh * NPIX * DH;
    const float *vb = g_v + (size_t)bh * DH * NPIX;
    const float *pb = g_p + (size_t)h * NPIX * DH;

    // stage a = [q_i | pos_i]
    #pragma unroll
    for (int l4 = 0; l4 < 4; l4++) {
        int c = t + l4 * 256;
        int i = c >> 4, d4 = (c & 15) * 4;
        float4 qv = *(const float4 *)&qb[(size_t)(i0 + i) * DH + d4];
        float4 pv = *(const float4 *)&pb[(size_t)(i0 + i) * DH + d4];
        float *ar = &as[i * 130];
        *(float2 *)&ar[d4]          = make_float2(qv.x, qv.y);
        *(float2 *)&ar[d4 + 2]      = make_float2(qv.z, qv.w);
        *(float2 *)&ar[64 + d4]     = make_float2(pv.x, pv.y);
        *(float2 *)&ar[64 + d4 + 2] = make_float2(pv.z, pv.w);
    }

    float mrow[4], lrow[4];
    u64 O2[4][4];
    #pragma unroll
    for (int ii = 0; ii < 4; ii++) {
        mrow[ii] = -1e30f; lrow[ii] = 0.f;
        #pragma unroll
        for (int dd = 0; dd < 4; dd++) O2[ii][dd] = 0ull;
    }

    for (int kt = 0; kt < 16; kt++) {
        const int j0 = kt * 64;
        __syncthreads();   // prev O-GEMM done reading vT/ps before restage
        // stage b = [k_j | q_j] and vT[d][j]
        #pragma unroll
        for (int l4 = 0; l4 < 4; l4++) {
            int c = t + l4 * 256;
            int j = c >> 4, d4 = (c & 15) * 4;
            float4 kv = *(const float4 *)&kb[(size_t)(j0 + j) * DH + d4];
            float4 qv = *(const float4 *)&qb[(size_t)(j0 + j) * DH + d4];
            float *br = &bs[j * 130];
            *(float2 *)&br[d4]          = make_float2(kv.x, kv.y);
            *(float2 *)&br[d4 + 2]      = make_float2(kv.z, kv.w);
            *(float2 *)&br[64 + d4]     = make_float2(qv.x, qv.y);
            *(float2 *)&br[64 + d4 + 2] = make_float2(qv.z, qv.w);
            // vT: row d = c>>4, cols j0 + (c&15)*4 (coalesced from g_v[bh][d][n])
            float4 vv = *(const float4 *)&vb[(size_t)j * NPIX + j0 + d4];
            float *vr = &vT[j * 66];
            *(float2 *)&vr[d4]     = make_float2(vv.x, vv.y);
            *(float2 *)&vr[d4 + 2] = make_float2(vv.z, vv.w);
        }
        __syncthreads();

        // ---- S = a.b (64x64, reduce 128, f32x2 packed along k) ----
        u64 acc2[4][4];
        #pragma unroll
        for (int ii = 0; ii < 4; ii++)
            #pragma unroll
            for (int jj = 0; jj < 4; jj++) acc2[ii][jj] = 0ull;
        #pragma unroll 8
        for (int kp = 0; kp < 64; kp++) {
            u64 a2[4], b2[4];
            #pragma unroll
            for (int ii = 0; ii < 4; ii++)
                a2[ii] = *(const u64 *)&as[(16 * ii + ty) * 130 + 2 * kp];
            #pragma unroll
            for (int jj = 0; jj < 4; jj++)
                b2[jj] = *(const u64 *)&bs[(16 * jj + tx) * 130 + 2 * kp];
            #pragma unroll
            for (int ii = 0; ii < 4; ii++)
                #pragma unroll
                for (int jj = 0; jj < 4; jj++) ffma2(acc2[ii][jj], a2[ii], b2[jj]);
        }

        // ---- online softmax ----
        float s[4][4];
        #pragma unroll
        for (int ii = 0; ii < 4; ii++)
            #pragma unroll
            for (int jj = 0; jj < 4; jj++) {
                float lo_, hi_; unpack2(acc2[ii][jj], lo_, hi_);
                s[ii][jj] = lo_ + hi_;
            }
        #pragma unroll
        for (int ii = 0; ii < 4; ii++) {
            float tmax = fmaxf(fmaxf(s[ii][0], s[ii][1]), fmaxf(s[ii][2], s[ii][3]));
            #pragma unroll
            for (int off = 1; off < 16; off <<= 1)
                tmax = fmaxf(tmax, __shfl_xor_sync(0xffffffffu, tmax, off));
            float nm = fmaxf(mrow[ii], tmax);
            float sc = __expf(mrow[ii] - nm);
            mrow[ii] = nm;
            float tsum = 0.f;
            #pragma unroll
            for (int jj = 0; jj < 4; jj++) {
                float pv = __expf(s[ii][jj] - nm);
                s[ii][jj] = pv;
                tsum += pv;
            }
            #pragma unroll
            for (int off = 1; off < 16; off <<= 1)
                tsum += __shfl_xor_sync(0xffffffffu, tsum, off);
            lrow[ii] = lrow[ii] * sc + tsum;
            u64 sc2 = pack2(sc, sc);
            #pragma unroll
            for (int dd = 0; dd < 4; dd++) O2[ii][dd] = mul2(O2[ii][dd], sc2);
            float *pr = &ps[(16 * ii + ty) * 80];
            #pragma unroll
            for (int jj = 0; jj < 4; jj++) pr[16 * jj + tx] = s[ii][jj];
        }
        __syncthreads();

        // ---- O += P.V (reduce 64 over j, f32x2 packed along j) ----
        #pragma unroll 8
        for (int jp = 0; jp < 32; jp++) {
            u64 p2[4], v2[4];
            #pragma unroll
            for (int ii = 0; ii < 4; ii++)
                p2[ii] = *(const u64 *)&ps[(16 * ii + ty) * 80 + 2 * jp];
            #pragma unroll
            for (int dd = 0; dd < 4; dd++)
                v2[dd] = *(const u64 *)&vT[(16 * dd + tx) * 66 + 2 * jp];
            #pragma unroll
            for (int ii = 0; ii < 4; ii++)
                #pragma unroll
                for (int dd = 0; dd < 4; dd++) ffma2(O2[ii][dd], p2[ii], v2[dd]);
        }
    }

    // ---- epilogue: normalize, stage O^T[d][i], coalesced store ----
    float rl[4];
    #pragma unroll
    for (int ii = 0; ii < 4; ii++) rl[ii] = 1.0f / lrow[ii];
    __syncthreads();
    #pragma unroll
    for (int dd = 0; dd < 4; dd++)
        #pragma unroll
        for (int ii = 0; ii < 4; ii++) {
            float lo_, hi_; unpack2(O2[ii][dd], lo_, hi_);
            vT[(16 * dd + tx) * 66 + 16 * ii + ty] = (lo_ + hi_) * rl[ii];
        }
    __syncthreads();
    {
        const int bidx = bh >> 3;
        int dcol = t >> 2;
        int ig   = (t & 3) * 16;
        const float *vr = &vT[dcol * 66 + ig];
        float *obase = out + ((size_t)bidx * 512 + h * 64 + dcol) * NPIX + i0 + ig;
        #pragma unroll
        for (int e = 0; e < 4; e++) {
            float2 u = *(const float2 *)&vr[4 * e];
            float2 w = *(const float2 *)&vr[4 * e + 2];
            *(float4 *)&obase[4 * e] = make_float4(u.x, u.y, w.x, w.y);
        }
    }
}

// ================= launch =================
extern "C" void kernel_launch(void *const *d_in, const int *in_sizes, int n_in,
                              void *d_out, int out_size) {
    const float *x     = (const float *)d_in[0];
    const float *d     = (const float *)d_in[1];
    const float *Wq    = (const float *)d_in[2];
    const float *bq    = (const float *)d_in[3];
    const float *Wk    = (const float *)d_in[4];
    const float *bk    = (const float *)d_in[5];
    const float *Wv    = (const float *)d_in[6];
    const float *bv    = (const float *)d_in[7];
    const float *rel_h = (const float *)d_in[8];
    const float *rel_w = (const float *)d_in[9];
    float *out = (float *)d_out;

    cudaFuncSetAttribute(attn_kernel,
                         cudaFuncAttributeMaxDynamicSharedMemorySize, ATTN_SMEM);

    pos_kernel<<<HEADS * NPIX * DH / 256, 256>>>(rel_h, rel_w);
    proj_kernel<<<dim3(64, NB, 3), 256>>>(x, d, Wq, bq, Wk, bk, Wv, bv);
    attn_kernel<<<dim3(16, NBH), 256, ATTN_SMEM>>>(out);
}

// round 3
// speedup vs baseline: 1.0792x; 1.0792x over previous
#include <cuda_runtime.h>

#define HEADS 8
#define DH    64
#define NPIX  1024
#define CC    512
#define NB    8
#define NBH   64

typedef unsigned long long u64;

// ---- scratch (device globals: allocation-guard-safe) ----
__device__ __align__(16) float g_q[NBH * NPIX * DH];   // [bh][n][d]
__device__ __align__(16) float g_k[NBH * NPIX * DH];   // [bh][n][d]
__device__ __align__(16) float g_v[NBH * DH * NPIX];   // [bh][d][n]  (transposed)
__device__ __align__(16) float g_p[HEADS * NPIX * DH]; // [h][n][d]

// ---- packed f32x2 helpers (Blackwell FFMA2 path) ----
__device__ __forceinline__ void ffma2(u64 &c, u64 a, u64 b) {
    asm("fma.rn.f32x2 %0, %1, %2, %0;" : "+l"(c) : "l"(a), "l"(b));
}
__device__ __forceinline__ u64 pack2(float x, float y) {
    u64 r; asm("mov.b64 %0, {%1, %2};" : "=l"(r) : "f"(x), "f"(y)); return r;
}
__device__ __forceinline__ void unpack2(u64 v, float &x, float &y) {
    asm("mov.b64 {%0, %1}, %2;" : "=f"(x), "=f"(y) : "l"(v));
}
__device__ __forceinline__ u64 mul2(u64 a, u64 b) {
    u64 r; asm("mul.rn.f32x2 %0, %1, %2;" : "=l"(r) : "l"(a), "l"(b)); return r;
}

// ================= pos = rel_h + rel_w -> g_p[h][n][d] =================
__global__ void pos_kernel(const float *__restrict__ rel_h,
                           const float *__restrict__ rel_w) {
    int idx = blockIdx.x * 256 + threadIdx.x;       // (h*1024+n)*64+d
    int d  = idx & 63;
    int n  = (idx >> 6) & 1023;
    int h  = idx >> 16;
    int w  = n >> 5;
    int hh = n & 31;
    g_p[idx] = rel_h[(h * DH + d) * 32 + hh] + rel_w[(h * DH + d) * 32 + w];
}

// ================= projection GEMMs =================
// Block tile: 128 pixels (m) x 128 out-channels (o) x k16. 256 threads, occ 2.
// Thread: tm = t&15 owns m pairs {2tm+32g, +1} (g<4); to = t>>4 owns o = to*8+j (j<8).
// f32x2 packing along free m-dim; B duplicated in smem (to-broadcast ulonglong2 reads).
__global__ __launch_bounds__(256, 2) void proj_kernel(
    const float *__restrict__ x,  const float *__restrict__ dsrc,
    const float *__restrict__ Wq, const float *__restrict__ bq,
    const float *__restrict__ Wk, const float *__restrict__ bk,
    const float *__restrict__ Wv, const float *__restrict__ bv) {
    const int p = blockIdx.z;
    const int b = blockIdx.y;
    const float *src  = (p == 0) ? x  : dsrc;
    const float *W    = (p == 0) ? Wq : (p == 1 ? Wk : Wv);
    const float *bias = (p == 0) ? bq : (p == 1 ? bk : bv);
    float *dst        = (p == 0) ? g_q : (p == 1 ? g_k : g_v);

    const int m0 = (blockIdx.x >> 2) * 128;
    const int o0 = (blockIdx.x & 3) * 128;

    __shared__ float As[16 * 130];                 // [k][m], m-contiguous
    __shared__ __align__(16) float Bs2[16 * 260];  // [k][2o] duplicated pairs

    const int t  = threadIdx.x;
    const int tm = t & 15;
    const int to = t >> 4;

    u64 acc2[4][8];
    #pragma unroll
    for (int g = 0; g < 4; g++)
        #pragma unroll
        for (int j = 0; j < 8; j++) acc2[g][j] = 0ull;

    const float *srcb = src + (size_t)b * CC * NPIX;

    for (int kt = 0; kt < 32; kt++) {
        const int k0 = kt * 16;
        // stage A: x[b][k0+k][m0..m0+127]
        #pragma unroll
        for (int l2 = 0; l2 < 2; l2++) {
            int c = t + l2 * 256;
            int k = c >> 5, m4 = (c & 31) * 4;
            float4 xv = *(const float4 *)&srcb[(size_t)(k0 + k) * NPIX + m0 + m4];
            float *ar = &As[k * 130 + m4];
            *(float2 *)ar       = make_float2(xv.x, xv.y);
            *(float2 *)(ar + 2) = make_float2(xv.z, xv.w);
        }
        // stage B duplicated: W[o0+o][k0..k0+15]; thread: o = t>>1, k8 = (t&1)*8
        {
            int o = t >> 1, k8 = (t & 1) * 8;
            float4 w0 = *(const float4 *)&W[(size_t)(o0 + o) * CC + k0 + k8];
            float4 w1 = *(const float4 *)&W[(size_t)(o0 + o) * CC + k0 + k8 + 4];
            float vals[8] = {w0.x, w0.y, w0.z, w0.w, w1.x, w1.y, w1.z, w1.w};
            #pragma unroll
            for (int e = 0; e < 8; e++)
                *(float2 *)&Bs2[(k8 + e) * 260 + 2 * o] = make_float2(vals[e], vals[e]);
        }
        __syncthreads();
        #pragma unroll 4
        for (int k = 0; k < 16; k++) {
            u64 a2[4];
            #pragma unroll
            for (int g = 0; g < 4; g++)
                a2[g] = *(const u64 *)&As[k * 130 + 2 * tm + 32 * g];
            ulonglong2 bv[4];
            #pragma unroll
            for (int jc = 0; jc < 4; jc++)
                bv[jc] = *(const ulonglong2 *)&Bs2[k * 260 + 16 * to + 4 * jc];
            #pragma unroll
            for (int g = 0; g < 4; g++)
                #pragma unroll
                for (int jc = 0; jc < 4; jc++) {
                    ffma2(acc2[g][2 * jc],     a2[g], bv[jc].x);
                    ffma2(acc2[g][2 * jc + 1], a2[g], bv[jc].y);
                }
        }
        __syncthreads();
    }

    // epilogue
    const int o_base = o0 + to * 8;
    float bia[8];
    #pragma unroll
    for (int j = 0; j < 8; j++) bia[j] = bias[o_base + j];
    const int head = o_base >> 6;
    const int d0   = o_base & 63;
    const int bh   = b * 8 + head;

    if (p < 2) {
        float *dbase = dst + (size_t)bh * NPIX * DH;
        #pragma unroll
        for (int g = 0; g < 4; g++) {
            int mm = m0 + 2 * tm + 32 * g;
            float lo[8], hi[8];
            #pragma unroll
            for (int j = 0; j < 8; j++) {
                float l_, h_; unpack2(acc2[g][j], l_, h_);
                lo[j] = l_ + bia[j]; hi[j] = h_ + bia[j];
            }
            *(float4 *)&dbase[(size_t)mm * DH + d0] =
                make_float4(lo[0], lo[1], lo[2], lo[3]);
            *(float4 *)&dbase[(size_t)mm * DH + d0 + 4] =
                make_float4(lo[4], lo[5], lo[6], lo[7]);
            *(float4 *)&dbase[(size_t)(mm + 1) * DH + d0] =
                make_float4(hi[0], hi[1], hi[2], hi[3]);
            *(float4 *)&dbase[(size_t)(mm + 1) * DH + d0 + 4] =
                make_float4(hi[4], hi[5], hi[6], hi[7]);
        }
    } else {
        // V transposed: dst[bh][d][n]; pair (m, m+1) -> contiguous STG.64
        float *dbase = dst + (size_t)bh * DH * NPIX;
        #pragma unroll
        for (int g = 0; g < 4; g++) {
            int mm = m0 + 2 * tm + 32 * g;
            #pragma unroll
            for (int j = 0; j < 8; j++) {
                float l_, h_; unpack2(acc2[g][j], l_, h_);
                *(float2 *)&dbase[(size_t)(d0 + j) * NPIX + mm] =
                    make_float2(l_ + bia[j], h_ + bia[j]);
            }
        }
    }
}

// ================= fused attention =================
// Block: (query tile 64, bh). 256 threads (tx=t&15, ty=t>>4), occ 2.
// S[i][j] = a_i . b_j, a=[q_i|pos_i], b=[k_j|q_j], reduce 128, f32x2 along k.
// a-loads LDS.128 broadcast (stride 132); b-loads LDS.64 conflict-free (stride 130).
#define ATTN_SMEM ((64 * 132 + 64 * 130 + 64 * 66 + 64 * 66) * 4)

__global__ __launch_bounds__(256, 2) void attn_kernel(float *__restrict__ out) {
    extern __shared__ __align__(16) float sm[];
    float *as = sm;                  // [64][132]: [q_i | pos_i] (16B-aligned rows)
    float *bs = as + 64 * 132;       // [64][130]: [k_j | q_j]
    float *vT = bs + 64 * 130;       // [64][66]:  v^T [d][j]
    float *ps = vT + 64 * 66;        // [64][66]:  P [i][j]

    const int t  = threadIdx.x;
    const int tx = t & 15;
    const int ty = t >> 4;
    const int i0 = blockIdx.x * 64;
    const int bh = blockIdx.y;
    const int h  = bh & 7;

    const float *qb = g_q + (size_t)bh * NPIX * DH;
    const float *kb = g_k + (size_t)bh * NPIX * DH;
    const float *vb = g_v + (size_t)bh * DH * NPIX;
    const float *pb = g_p + (size_t)h * NPIX * DH;

    // stage a = [q_i | pos_i]
    #pragma unroll
    for (int l4 = 0; l4 < 4; l4++) {
        int c = t + l4 * 256;
        int i = c >> 4, d4 = (c & 15) * 4;
        *(float4 *)&as[i * 132 + d4]      = *(const float4 *)&qb[(size_t)(i0 + i) * DH + d4];
        *(float4 *)&as[i * 132 + 64 + d4] = *(const float4 *)&pb[(size_t)(i0 + i) * DH + d4];
    }

    float mrow[4], lrow[4];
    u64 O2[4][4];
    #pragma unroll
    for (int ii = 0; ii < 4; ii++) {
        mrow[ii] = -1e30f; lrow[ii] = 0.f;
        #pragma unroll
        for (int dd = 0; dd < 4; dd++) O2[ii][dd] = 0ull;
    }

    for (int kt = 0; kt < 16; kt++) {
        const int j0 = kt * 64;
        __syncthreads();   // prev PV done reading vT/ps before restage
        // stage b = [k_j | q_j] (stride 130, float2 stores) and vT[d][j]
        #pragma unroll
        for (int l4 = 0; l4 < 4; l4++) {
            int c = t + l4 * 256;
            int j = c >> 4, d4 = (c & 15) * 4;
            float4 kv = *(const float4 *)&kb[(size_t)(j0 + j) * DH + d4];
            float4 qv = *(const float4 *)&qb[(size_t)(j0 + j) * DH + d4];
            float *br = &bs[j * 130];
            *(float2 *)&br[d4]          = make_float2(kv.x, kv.y);
            *(float2 *)&br[d4 + 2]      = make_float2(kv.z, kv.w);
            *(float2 *)&br[64 + d4]     = make_float2(qv.x, qv.y);
            *(float2 *)&br[64 + d4 + 2] = make_float2(qv.z, qv.w);
            float4 vv = *(const float4 *)&vb[(size_t)j * NPIX + j0 + d4];
            float *vr = &vT[j * 66];
            *(float2 *)&vr[d4]     = make_float2(vv.x, vv.y);
            *(float2 *)&vr[d4 + 2] = make_float2(vv.z, vv.w);
        }
        __syncthreads();

        // ---- S = a.b (64x64, reduce 128, f32x2 along k, 4-k steps) ----
        u64 acc2[4][4];
        #pragma unroll
        for (int ii = 0; ii < 4; ii++)
            #pragma unroll
            for (int jj = 0; jj < 4; jj++) acc2[ii][jj] = 0ull;
        #pragma unroll 8
        for (int kq = 0; kq < 32; kq++) {
            const int k4 = 4 * kq;
            ulonglong2 a4[4];
            #pragma unroll
            for (int ii = 0; ii < 4; ii++)
                a4[ii] = *(const ulonglong2 *)&as[(16 * ii + ty) * 132 + k4];
            u64 b2a[4], b2b[4];
            #pragma unroll
            for (int jj = 0; jj < 4; jj++) {
                const float *br = &bs[(16 * jj + tx) * 130 + k4];
                b2a[jj] = *(const u64 *)br;
                b2b[jj] = *(const u64 *)(br + 2);
            }
            #pragma unroll
            for (int ii = 0; ii < 4; ii++)
                #pragma unroll
                for (int jj = 0; jj < 4; jj++) {
                    ffma2(acc2[ii][jj], a4[ii].x, b2a[jj]);
                    ffma2(acc2[ii][jj], a4[ii].y, b2b[jj]);
                }
        }

        // ---- online softmax ----
        float s[4][4];
        #pragma unroll
        for (int ii = 0; ii < 4; ii++)
            #pragma unroll
            for (int jj = 0; jj < 4; jj++) {
                float lo_, hi_; unpack2(acc2[ii][jj], lo_, hi_);
                s[ii][jj] = lo_ + hi_;
            }
        #pragma unroll
        for (int ii = 0; ii < 4; ii++) {
            float tmax = fmaxf(fmaxf(s[ii][0], s[ii][1]), fmaxf(s[ii][2], s[ii][3]));
            #pragma unroll
            for (int off = 1; off < 16; off <<= 1)
                tmax = fmaxf(tmax, __shfl_xor_sync(0xffffffffu, tmax, off));
            float nm = fmaxf(mrow[ii], tmax);
            float sc = __expf(mrow[ii] - nm);
            mrow[ii] = nm;
            float tsum = 0.f;
            #pragma unroll
            for (int jj = 0; jj < 4; jj++) {
                float pv = __expf(s[ii][jj] - nm);
                s[ii][jj] = pv;
                tsum += pv;
            }
            #pragma unroll
            for (int off = 1; off < 16; off <<= 1)
                tsum += __shfl_xor_sync(0xffffffffu, tsum, off);
            lrow[ii] = lrow[ii] * sc + tsum;
            u64 sc2 = pack2(sc, sc);
            #pragma unroll
            for (int dd = 0; dd < 4; dd++) O2[ii][dd] = mul2(O2[ii][dd], sc2);
            float *pr = &ps[(16 * ii + ty) * 66];
            #pragma unroll
            for (int jj = 0; jj < 4; jj++) pr[16 * jj + tx] = s[ii][jj];
        }
        __syncthreads();

        // ---- O += P.V (reduce 64 over j, f32x2 along j) ----
        #pragma unroll 8
        for (int jp = 0; jp < 32; jp++) {
            u64 p2[4], v2[4];
            #pragma unroll
            for (int ii = 0; ii < 4; ii++)
                p2[ii] = *(const u64 *)&ps[(16 * ii + ty) * 66 + 2 * jp];
            #pragma unroll
            for (int dd = 0; dd < 4; dd++)
                v2[dd] = *(const u64 *)&vT[(16 * dd + tx) * 66 + 2 * jp];
            #pragma unroll
            for (int ii = 0; ii < 4; ii++)
                #pragma unroll
                for (int dd = 0; dd < 4; dd++) ffma2(O2[ii][dd], p2[ii], v2[dd]);
        }
    }

    // ---- epilogue: normalize, stage O^T[d][i] in as-region, coalesced store ----
    float rl[4];
    #pragma unroll
    for (int ii = 0; ii < 4; ii++) rl[ii] = 1.0f / lrow[ii];
    __syncthreads();               // done with as (S-GEMM reads)
    float *ot = as;                // [64 d][68]
    #pragma unroll
    for (int dd = 0; dd < 4; dd++)
        #pragma unroll
        for (int ii = 0; ii < 4; ii++) {
            float lo_, hi_; unpack2(O2[ii][dd], lo_, hi_);
            ot[(16 * dd + tx) * 68 + 16 * ii + ty] = (lo_ + hi_) * rl[ii];
        }
    __syncthreads();
    {
        const int bidx = bh >> 3;
        int dcol = t >> 2;
        int ig   = (t & 3) * 16;
        const float *vr = &ot[dcol * 68 + ig];
        float *obase = out + ((size_t)bidx * 512 + h * 64 + dcol) * NPIX + i0 + ig;
        #pragma unroll
        for (int e = 0; e < 4; e++)
            *(float4 *)&obase[4 * e] = *(const float4 *)&vr[4 * e];
    }
}

// ================= launch =================
extern "C" void kernel_launch(void *const *d_in, const int *in_sizes, int n_in,
                              void *d_out, int out_size) {
    const float *x     = (const float *)d_in[0];
    const float *d     = (const float *)d_in[1];
    const float *Wq    = (const float *)d_in[2];
    const float *bq    = (const float *)d_in[3];
    const float *Wk    = (const float *)d_in[4];
    const float *bk    = (const float *)d_in[5];
    const float *Wv    = (const float *)d_in[6];
    const float *bv    = (const float *)d_in[7];
    const float *rel_h = (const float *)d_in[8];
    const float *rel_w = (const float *)d_in[9];
    float *out = (float *)d_out;

    cudaFuncSetAttribute(attn_kernel,
                         cudaFuncAttributeMaxDynamicSharedMemorySize, ATTN_SMEM);

    pos_kernel<<<HEADS * NPIX * DH / 256, 256>>>(rel_h, rel_w);
    proj_kernel<<<dim3(32, NB, 3), 256>>>(x, d, Wq, bq, Wk, bk, Wv, bv);
    attn_kernel<<<dim3(16, NBH), 256, ATTN_SMEM>>>(out);
}